// round 1
// baseline (speedup 1.0000x reference)
#include <cuda_runtime.h>
#include <stdint.h>

// GreedyGroupedRouter: SEQ=524288 tokens, 256 experts, 8 groups of 32, top-1 per group.
// Outputs (all float32, concatenated in d_out):
//   [0)                routing_weights  SEQ*256
//   [SEQ*256)          topk_weights     SEQ*8
//   [SEQ*264)          topk_ids         SEQ*8   (integer values stored as float)
//   [SEQ*272)          tokens_per_expert 256

#define SEQ     524288
#define NE      256
#define NG      8
#define GS      32
#define TOPK    8

__global__ void zero_hist_kernel(float* hist) {
    hist[threadIdx.x] = 0.0f;
}

__global__ void __launch_bounds__(256)
router_kernel(const float* __restrict__ logits,
              float* __restrict__ rw,     // [SEQ, 256]
              float* __restrict__ tw,     // [SEQ, 8]
              float* __restrict__ tids,   // [SEQ, 8]
              float* __restrict__ hist)   // [256]
{
    __shared__ unsigned int shist[NE];
    for (int i = threadIdx.x; i < NE; i += blockDim.x) shist[i] = 0u;
    __syncthreads();

    const int lane     = threadIdx.x & 31;
    const int warp_ib  = threadIdx.x >> 5;
    const int wpb      = blockDim.x >> 5;
    const int gwarp    = blockIdx.x * wpb + warp_ib;
    const int nwarps   = gridDim.x * wpb;

    for (int row = gwarp; row < SEQ; row += nwarps) {
        const float* lp = logits + (size_t)row * NE;

        // Lane-strided load: lane holds element (lane + 32*i) -> element i is
        // this lane's member of expert-group i. Each load is a coalesced 128B.
        float x[NG];
        #pragma unroll
        for (int i = 0; i < NG; i++) x[i] = lp[lane + GS * i];

        // Row max (softmax stabilization)
        float m = x[0];
        #pragma unroll
        for (int i = 1; i < NG; i++) m = fmaxf(m, x[i]);
        #pragma unroll
        for (int o = 16; o > 0; o >>= 1)
            m = fmaxf(m, __shfl_xor_sync(0xffffffffu, m, o));

        // exp + row sum
        float e[NG];
        float s = 0.0f;
        #pragma unroll
        for (int i = 0; i < NG; i++) { e[i] = __expf(x[i] - m); s += e[i]; }
        #pragma unroll
        for (int o = 16; o > 0; o >>= 1)
            s += __shfl_xor_sync(0xffffffffu, s, o);
        const float inv = 1.0f / s;

        // Softmax weights + streaming store of routing_weights
        float* rp = rw + (size_t)row * NE;
        float w[NG];
        #pragma unroll
        for (int i = 0; i < NG; i++) {
            w[i] = e[i] * inv;
            rp[lane + GS * i] = w[i];
        }

        // Per-group argmax (group g = lanes' w[g]); tie-break to lowest lane
        // index, matching jax.lax.top_k. Softmax values are in (0,1], so the
        // float bit pattern is monotone as unsigned.
        float myw  = 0.0f;   // valid on lanes 0..7
        float myid = 0.0f;
        float sw   = 0.0f;
        #pragma unroll
        for (int g = 0; g < NG; g++) {
            unsigned u    = __float_as_uint(w[g]);
            unsigned umax = __reduce_max_sync(0xffffffffu, u);
            unsigned bal  = __ballot_sync(0xffffffffu, u == umax);
            int src       = __ffs(bal) - 1;           // lowest winning lane
            float gv      = __uint_as_float(umax);
            sw += gv;
            if (lane == g) { myw = gv; myid = (float)(g * GS + src); }
            if (lane == src) atomicAdd(&shist[g * GS + src], 1u);
        }
        const float invsw = 1.0f / (sw + 1e-20f);

        if (lane < TOPK) {
            tw[(size_t)row * TOPK + lane]   = myw * invsw;
            tids[(size_t)row * TOPK + lane] = myid;
        }
    }

    __syncthreads();
    for (int i = threadIdx.x; i < NE; i += blockDim.x) {
        unsigned c = shist[i];
        if (c) atomicAdd(&hist[i], (float)c);
    }
}

extern "C" void kernel_launch(void* const* d_in, const int* in_sizes, int n_in,
                              void* d_out, int out_size) {
    const float* logits = (const float*)d_in[0];
    float* out  = (float*)d_out;
    float* rw   = out;
    float* tw   = rw   + (size_t)SEQ * NE;
    float* tids = tw   + (size_t)SEQ * TOPK;
    float* hist = tids + (size_t)SEQ * TOPK;

    zero_hist_kernel<<<1, NE>>>(hist);
    // 1184 blocks x 256 threads = 9472 warps, ~55 rows per warp (grid-stride).
    router_kernel<<<1184, 256>>>(logits, rw, tw, tids, hist);
}